// round 1
// baseline (speedup 1.0000x reference)
#include <cuda_runtime.h>
#include <cstdint>

#define NQ   4
#define DIM  16
#define NC   4
#define BLK  256

// Global accumulators: [0..3] = sum(logit_c), [4..7] = sum(logit_c^2)
__device__ double g_acc[8];
__device__ float  g_scale[NC];
__device__ float  g_shift[NC];

__global__ void k_zero() {
    if (threadIdx.x < 8) g_acc[threadIdx.x] = 0.0;
}

__global__ __launch_bounds__(BLK) void k_main(
    const float* __restrict__ x,      // [B, 144]
    const float* __restrict__ wts,    // [8]
    const float* __restrict__ W,      // [NC, NQ] row-major
    const float* __restrict__ bias,   // [NC]
    float* __restrict__ out,          // [B, NC]
    int B)
{
    const int b = blockIdx.x * blockDim.x + threadIdx.x;

    float logit[4] = {0.f, 0.f, 0.f, 0.f};
    bool active = (b < B);

    if (active) {
        // ---- RY weight angles (broadcast loads, L1/L2 cached) ----
        float wc[8], ws[8];
        #pragma unroll
        for (int i = 0; i < 8; i++) __sincosf(wts[i] * 0.5f, &ws[i], &wc[i]);

        // ---- avg_pool2d 6x6 over [12,12]: 36 float4 loads per row ----
        const float4* xp = (const float4*)(x + (size_t)b * 144);
        float s0 = 0.f, s1 = 0.f, s2 = 0.f, s3 = 0.f;
        #pragma unroll
        for (int r = 0; r < 12; r++) {
            float4 v0 = xp[r * 3 + 0];
            float4 v1 = xp[r * 3 + 1];
            float4 v2 = xp[r * 3 + 2];
            float left  = v0.x + v0.y + v0.z + v0.w + v1.x + v1.y;
            float right = v1.z + v1.w + v2.x + v2.y + v2.z + v2.w;
            if (r < 6) { s0 += left; s1 += right; }
            else       { s2 += left; s3 += right; }
        }
        const float inv36 = 1.f / 36.f;
        float pc4[4], ps4[4];
        __sincosf(s0 * inv36 * 0.5f, &ps4[0], &pc4[0]);
        __sincosf(s1 * inv36 * 0.5f, &ps4[1], &pc4[1]);
        __sincosf(s2 * inv36 * 0.5f, &ps4[2], &pc4[2]);
        __sincosf(s3 * inv36 * 0.5f, &ps4[3], &pc4[3]);

        // ---- initial state after RX embed: amp[k] = (-i)^pc(k) * prod ----
        // wire w <-> bit (3-w)
        float re[DIM], im[DIM];
        #pragma unroll
        for (int k = 0; k < DIM; k++) {
            float m = ((k & 8) ? ps4[0] : pc4[0])
                    * ((k & 4) ? ps4[1] : pc4[1])
                    * ((k & 2) ? ps4[2] : pc4[2])
                    * ((k & 1) ? ps4[3] : pc4[3]);
            int pc = __popc(k) & 3;
            re[k] = (pc == 0) ? m : ((pc == 2) ? -m : 0.f);
            im[k] = (pc == 1) ? -m : ((pc == 3) ? m : 0.f);
        }

        // ---- DEPTH x (RY layer + CZ chain); all-real operators ----
        int idx = 0;
        #pragma unroll
        for (int d = 0; d < 2; d++) {
            #pragma unroll
            for (int w = 0; w < NQ; w++) {
                float cc = wc[idx], ss = ws[idx]; idx++;
                int bit = 1 << (3 - w);
                #pragma unroll
                for (int k = 0; k < DIM; k++) {
                    if (!(k & bit)) {
                        int k1 = k | bit;
                        float r0 = re[k], r1 = re[k1];
                        re[k]  = cc * r0 - ss * r1;
                        re[k1] = ss * r0 + cc * r1;
                        float i0 = im[k], i1 = im[k1];
                        im[k]  = cc * i0 - ss * i1;
                        im[k1] = ss * i0 + cc * i1;
                    }
                }
            }
            // CZ chain: sign = (-1)^(# adjacent set-bit pairs)
            #pragma unroll
            for (int k = 0; k < DIM; k++) {
                int par = (((k >> 3) & (k >> 2)) ^ ((k >> 2) & (k >> 1)) ^ ((k >> 1) & k)) & 1;
                if (par) { re[k] = -re[k]; im[k] = -im[k]; }
            }
        }

        // ---- probs -> Z expvals ----
        float q0 = 0.f, q1 = 0.f, q2 = 0.f, q3 = 0.f;
        #pragma unroll
        for (int k = 0; k < DIM; k++) {
            float p = re[k] * re[k] + im[k] * im[k];
            q0 += (k & 8) ? -p : p;
            q1 += (k & 4) ? -p : p;
            q2 += (k & 2) ? -p : p;
            q3 += (k & 1) ? -p : p;
        }

        // ---- linear head ----
        #pragma unroll
        for (int c = 0; c < NC; c++) {
            logit[c] = bias[c] + q0 * W[c * 4 + 0] + q1 * W[c * 4 + 1]
                               + q2 * W[c * 4 + 2] + q3 * W[c * 4 + 3];
        }
        ((float4*)out)[b] = make_float4(logit[0], logit[1], logit[2], logit[3]);
    }

    // ---- block reduction of sum & sumsq (inactive threads add zeros) ----
    float red[8];
    #pragma unroll
    for (int c = 0; c < 4; c++) {
        red[c]     = active ? logit[c] : 0.f;
        red[4 + c] = active ? logit[c] * logit[c] : 0.f;
    }
    #pragma unroll
    for (int off = 16; off > 0; off >>= 1) {
        #pragma unroll
        for (int j = 0; j < 8; j++)
            red[j] += __shfl_down_sync(0xFFFFFFFFu, red[j], off);
    }
    __shared__ float smem[8][BLK / 32];
    int lane = threadIdx.x & 31, warp = threadIdx.x >> 5;
    if (lane == 0) {
        #pragma unroll
        for (int j = 0; j < 8; j++) smem[j][warp] = red[j];
    }
    __syncthreads();
    if (threadIdx.x < 8) {
        float acc = 0.f;
        #pragma unroll
        for (int wgi = 0; wgi < BLK / 32; wgi++) acc += smem[threadIdx.x][wgi];
        atomicAdd(&g_acc[threadIdx.x], (double)acc);
    }
}

__global__ void k_stats(const float* __restrict__ gamma,
                        const float* __restrict__ beta, float invB) {
    int c = threadIdx.x;  // 0..3
    if (c < NC) {
        double m = g_acc[c] * (double)invB;
        double v = g_acc[4 + c] * (double)invB - m * m;
        float inv = rsqrtf((float)v + 1e-5f);
        g_scale[c] = gamma[c] * inv;
        g_shift[c] = beta[c] - (float)m * inv * gamma[c];
    }
}

__global__ __launch_bounds__(BLK) void k_norm(float* __restrict__ out, int B) {
    int b = blockIdx.x * blockDim.x + threadIdx.x;
    if (b >= B) return;
    float4 l = ((const float4*)out)[b];
    l.x = l.x * g_scale[0] + g_shift[0];
    l.y = l.y * g_scale[1] + g_shift[1];
    l.z = l.z * g_scale[2] + g_shift[2];
    l.w = l.w * g_scale[3] + g_shift[3];
    ((float4*)out)[b] = l;
}

extern "C" void kernel_launch(void* const* d_in, const int* in_sizes, int n_in,
                              void* d_out, int out_size) {
    const float* x     = (const float*)d_in[0];  // [B,1,12,12]
    const float* wts   = (const float*)d_in[1];  // [8]
    const float* W     = (const float*)d_in[2];  // [4,4]
    const float* bias  = (const float*)d_in[3];  // [4]
    const float* gamma = (const float*)d_in[4];  // [4]
    const float* beta  = (const float*)d_in[5];  // [4]
    float* out = (float*)d_out;

    int B = in_sizes[0] / 144;
    int grid = (B + BLK - 1) / BLK;

    k_zero<<<1, 32>>>();
    k_main<<<grid, BLK>>>(x, wts, W, bias, out, B);
    k_stats<<<1, 32>>>(gamma, beta, 1.0f / (float)B);
    k_norm<<<grid, BLK>>>(out, B);
}

// round 2
// speedup vs baseline: 1.0577x; 1.0577x over previous
#include <cuda_runtime.h>
#include <cstdint>

#define NQ   4
#define DIM  16
#define NC   4
#define BLK  256
#define ROWS_PER_BLK 256
#define CHUNK 64
#define NCHUNK 4
#define PITCH 148   // floats per row in smem: 148 mod 32 = 20 -> LDS.128 at crossbar floor

// Global accumulators: [0..3] = sum(logit_c), [4..7] = sum(logit_c^2)
__device__ double g_acc[8];
__device__ float  g_scale[NC];
__device__ float  g_shift[NC];

__global__ void k_zero() {
    if (threadIdx.x < 8) g_acc[threadIdx.x] = 0.0;
}

__global__ __launch_bounds__(BLK) void k_main(
    const float* __restrict__ x,      // [B, 144]
    const float* __restrict__ wts,    // [8]
    const float* __restrict__ W,      // [NC, NQ] row-major
    const float* __restrict__ bias,   // [NC]
    float* __restrict__ out,          // [B, NC]
    int B)
{
    __shared__ float sbuf[CHUNK * PITCH];   // 37888 B

    const int t = threadIdx.x;
    const int row_blk = blockIdx.x * ROWS_PER_BLK;

    // ---- staged, coalesced pooling ----
    float s0 = 0.f, s1 = 0.f, s2 = 0.f, s3 = 0.f;

    #pragma unroll
    for (int c = 0; c < NCHUNK; c++) {
        // coalesced load of 64 rows x 144 floats = 2304 float4, 9 per thread
        const float4* xsrc = (const float4*)(x + (size_t)(row_blk + c * CHUNK) * 144);
        #pragma unroll
        for (int k = 0; k < 9; k++) {
            int idx = t + k * BLK;
            float4 v = xsrc[idx];
            int row = idx / 36;
            int col4 = idx % 36;
            *(float4*)&sbuf[row * PITCH + col4 * 4] = v;
        }
        __syncthreads();

        // threads owning rows of this chunk pool from smem
        if ((t >> 6) == c) {
            int rl = t & 63;
            const float* rp = &sbuf[rl * PITCH];
            float a0 = 0.f, a1 = 0.f, a2 = 0.f, a3 = 0.f;
            #pragma unroll
            for (int r = 0; r < 12; r++) {
                float4 v0 = *(const float4*)&rp[r * 12 + 0];
                float4 v1 = *(const float4*)&rp[r * 12 + 4];
                float4 v2 = *(const float4*)&rp[r * 12 + 8];
                float left  = v0.x + v0.y + v0.z + v0.w + v1.x + v1.y;
                float right = v1.z + v1.w + v2.x + v2.y + v2.z + v2.w;
                if (r < 6) { a0 += left; a1 += right; }
                else       { a2 += left; a3 += right; }
            }
            s0 = a0; s1 = a1; s2 = a2; s3 = a3;
        }
        __syncthreads();
    }

    const int b = row_blk + t;   // this thread's row (B divisible by 256)

    // ---- RY weight angles (broadcast loads) ----
    float wc[8], ws[8];
    #pragma unroll
    for (int i = 0; i < 8; i++) __sincosf(wts[i] * 0.5f, &ws[i], &wc[i]);

    const float inv72 = 1.f / 72.f;   // (1/36) * 0.5
    float pc4[4], ps4[4];
    __sincosf(s0 * inv72, &ps4[0], &pc4[0]);
    __sincosf(s1 * inv72, &ps4[1], &pc4[1]);
    __sincosf(s2 * inv72, &ps4[2], &pc4[2]);
    __sincosf(s3 * inv72, &ps4[3], &pc4[3]);

    // ---- initial state after RX embed: amp[k] = (-i)^popc(k) * prod ----
    float re[DIM], im[DIM];
    #pragma unroll
    for (int k = 0; k < DIM; k++) {
        float m = ((k & 8) ? ps4[0] : pc4[0])
                * ((k & 4) ? ps4[1] : pc4[1])
                * ((k & 2) ? ps4[2] : pc4[2])
                * ((k & 1) ? ps4[3] : pc4[3]);
        int pc = __popc(k) & 3;
        re[k] = (pc == 0) ? m : ((pc == 2) ? -m : 0.f);
        im[k] = (pc == 1) ? -m : ((pc == 3) ? m : 0.f);
    }

    // ---- DEPTH x (RY layer + CZ chain); all-real operators ----
    int idx = 0;
    #pragma unroll
    for (int d = 0; d < 2; d++) {
        #pragma unroll
        for (int w = 0; w < NQ; w++) {
            float cc = wc[idx], ss = ws[idx]; idx++;
            int bit = 1 << (3 - w);
            #pragma unroll
            for (int k = 0; k < DIM; k++) {
                if (!(k & bit)) {
                    int k1 = k | bit;
                    float r0 = re[k], r1 = re[k1];
                    re[k]  = cc * r0 - ss * r1;
                    re[k1] = ss * r0 + cc * r1;
                    float i0 = im[k], i1 = im[k1];
                    im[k]  = cc * i0 - ss * i1;
                    im[k1] = ss * i0 + cc * i1;
                }
            }
        }
        // CZ chain: sign = parity of adjacent set-bit pairs
        #pragma unroll
        for (int k = 0; k < DIM; k++) {
            int par = (((k >> 3) & (k >> 2)) ^ ((k >> 2) & (k >> 1)) ^ ((k >> 1) & k)) & 1;
            if (par) { re[k] = -re[k]; im[k] = -im[k]; }
        }
    }

    // ---- probs -> Z expvals ----
    float q0 = 0.f, q1 = 0.f, q2 = 0.f, q3 = 0.f;
    #pragma unroll
    for (int k = 0; k < DIM; k++) {
        float p = re[k] * re[k] + im[k] * im[k];
        q0 += (k & 8) ? -p : p;
        q1 += (k & 4) ? -p : p;
        q2 += (k & 2) ? -p : p;
        q3 += (k & 1) ? -p : p;
    }

    // ---- linear head ----
    float logit[4];
    #pragma unroll
    for (int c = 0; c < NC; c++) {
        logit[c] = bias[c] + q0 * W[c * 4 + 0] + q1 * W[c * 4 + 1]
                           + q2 * W[c * 4 + 2] + q3 * W[c * 4 + 3];
    }
    ((float4*)out)[b] = make_float4(logit[0], logit[1], logit[2], logit[3]);

    // ---- block reduction of sum & sumsq ----
    float red[8];
    #pragma unroll
    for (int c = 0; c < 4; c++) {
        red[c]     = logit[c];
        red[4 + c] = logit[c] * logit[c];
    }
    #pragma unroll
    for (int off = 16; off > 0; off >>= 1) {
        #pragma unroll
        for (int j = 0; j < 8; j++)
            red[j] += __shfl_down_sync(0xFFFFFFFFu, red[j], off);
    }
    __shared__ float smem[8][BLK / 32];
    int lane = t & 31, warp = t >> 5;
    if (lane == 0) {
        #pragma unroll
        for (int j = 0; j < 8; j++) smem[j][warp] = red[j];
    }
    __syncthreads();
    if (t < 8) {
        float acc = 0.f;
        #pragma unroll
        for (int wgi = 0; wgi < BLK / 32; wgi++) acc += smem[t][wgi];
        atomicAdd(&g_acc[t], (double)acc);
    }
}

__global__ void k_stats(const float* __restrict__ gamma,
                        const float* __restrict__ beta, float invB) {
    int c = threadIdx.x;  // 0..3
    if (c < NC) {
        double m = g_acc[c] * (double)invB;
        double v = g_acc[4 + c] * (double)invB - m * m;
        float inv = rsqrtf((float)v + 1e-5f);
        g_scale[c] = gamma[c] * inv;
        g_shift[c] = beta[c] - (float)m * inv * gamma[c];
    }
}

// 4-way ILP normalize: B float4s processed by B/4 threads, interleaved for MLP=4
__global__ __launch_bounds__(BLK) void k_norm(float* __restrict__ out, int B) {
    int tid = blockIdx.x * blockDim.x + threadIdx.x;
    int S = gridDim.x * blockDim.x;           // B/4
    float sc0 = g_scale[0], sc1 = g_scale[1], sc2 = g_scale[2], sc3 = g_scale[3];
    float sh0 = g_shift[0], sh1 = g_shift[1], sh2 = g_shift[2], sh3 = g_shift[3];
    float4* o4 = (float4*)out;
    float4 a = o4[tid], bq = o4[tid + S], cq = o4[tid + 2 * S], dq = o4[tid + 3 * S];
    a.x  = a.x  * sc0 + sh0; a.y  = a.y  * sc1 + sh1; a.z  = a.z  * sc2 + sh2; a.w  = a.w  * sc3 + sh3;
    bq.x = bq.x * sc0 + sh0; bq.y = bq.y * sc1 + sh1; bq.z = bq.z * sc2 + sh2; bq.w = bq.w * sc3 + sh3;
    cq.x = cq.x * sc0 + sh0; cq.y = cq.y * sc1 + sh1; cq.z = cq.z * sc2 + sh2; cq.w = cq.w * sc3 + sh3;
    dq.x = dq.x * sc0 + sh0; dq.y = dq.y * sc1 + sh1; dq.z = dq.z * sc2 + sh2; dq.w = dq.w * sc3 + sh3;
    o4[tid] = a; o4[tid + S] = bq; o4[tid + 2 * S] = cq; o4[tid + 3 * S] = dq;
}

extern "C" void kernel_launch(void* const* d_in, const int* in_sizes, int n_in,
                              void* d_out, int out_size) {
    const float* x     = (const float*)d_in[0];  // [B,1,12,12]
    const float* wts   = (const float*)d_in[1];  // [8]
    const float* W     = (const float*)d_in[2];  // [4,4]
    const float* bias  = (const float*)d_in[3];  // [4]
    const float* gamma = (const float*)d_in[4];  // [4]
    const float* beta  = (const float*)d_in[5];  // [4]
    float* out = (float*)d_out;

    int B = in_sizes[0] / 144;                   // 262144
    int grid = (B + ROWS_PER_BLK - 1) / ROWS_PER_BLK;

    k_zero<<<1, 32>>>();
    k_main<<<grid, BLK>>>(x, wts, W, bias, out, B);
    k_stats<<<1, 32>>>(gamma, beta, 1.0f / (float)B);
    k_norm<<<B / (BLK * 4), BLK>>>(out, B);
}